// round 4
// baseline (speedup 1.0000x reference)
#include <cuda_runtime.h>
#include <cstdint>
#include <cstddef>

// Problem constants
#define BATCH 2
#define SEQ   2048
#define DM    768
#define NH    12
#define DHD   64
#define ATT_SCALE 0.125f   // 1/sqrt(64)

// Scratch (allocation-free rule: __device__ globals)
__device__ float g_q[BATCH * SEQ * DM];
__device__ float g_k[BATCH * SEQ * DM];
__device__ float g_v[BATCH * SEQ * DM];
__device__ float g_attn[BATCH * SEQ * DM];
__device__ float g_rowl[BATCH * NH * SEQ];   // softmax row sums

// ---------------------------------------------------------------------------
// tf32 helpers
// ---------------------------------------------------------------------------
__device__ __forceinline__ uint32_t f2tf32(float f) {
    uint32_t u;
    asm("cvt.rna.tf32.f32 %0, %1;" : "=r"(u) : "f"(f));
    return u;
}

__device__ __forceinline__ void mma8(float* c, const uint32_t* a, const uint32_t* b) {
    asm volatile(
        "mma.sync.aligned.m16n8k8.row.col.f32.tf32.tf32.f32 "
        "{%0,%1,%2,%3},{%4,%5,%6,%7},{%8,%9},{%0,%1,%2,%3};"
        : "+f"(c[0]), "+f"(c[1]), "+f"(c[2]), "+f"(c[3])
        : "r"(a[0]), "r"(a[1]), "r"(a[2]), "r"(a[3]), "r"(b[0]), "r"(b[1]));
}

// ===========================================================================
// init: zero row-sum accumulator
// ===========================================================================
__global__ void init_rowl()
{
    g_rowl[blockIdx.x * 256 + threadIdx.x] = 0.f;
}

// ===========================================================================
// Projection: Y[M,768] = X[M,768] @ W^T + bias.
// 128x128 CTA tile, BK=16, double-buffered smem + register prefetch.
// grid = (6, M/128), 256 threads (8 warps, 2x4; warp tile 64x32).
// ===========================================================================
__device__ __forceinline__ void proj_stage_load(
    const float* __restrict__ Ag, const float* __restrict__ Bg,
    int k0, int tid, float4 ar[2], float4 br[2])
{
    #pragma unroll
    for (int t = 0; t < 2; t++) {
        int i = tid + t * 256;
        ar[t] = *(const float4*)(Ag + (size_t)(i >> 2) * DM + k0 + (i & 3) * 4);
    }
    #pragma unroll
    for (int t = 0; t < 2; t++) {
        int i = tid + t * 256;
        br[t] = *(const float4*)(Bg + (size_t)(i >> 2) * DM + k0 + (i & 3) * 4);
    }
}

__device__ __forceinline__ void proj_stage_store(
    uint32_t As[16][136], uint32_t Bs[16][136],
    int tid, const float4 ar[2], const float4 br[2])
{
    #pragma unroll
    for (int t = 0; t < 2; t++) {
        int i = tid + t * 256;
        int r = i >> 2, c = (i & 3) * 4;
        As[c + 0][r] = f2tf32(ar[t].x);
        As[c + 1][r] = f2tf32(ar[t].y);
        As[c + 2][r] = f2tf32(ar[t].z);
        As[c + 3][r] = f2tf32(ar[t].w);
    }
    #pragma unroll
    for (int t = 0; t < 2; t++) {
        int i = tid + t * 256;
        int r = i >> 2, c = (i & 3) * 4;
        Bs[c + 0][r] = f2tf32(br[t].x);
        Bs[c + 1][r] = f2tf32(br[t].y);
        Bs[c + 2][r] = f2tf32(br[t].z);
        Bs[c + 3][r] = f2tf32(br[t].w);
    }
}

__device__ __forceinline__ void proj_tile_mma(
    const uint32_t As[16][136], const uint32_t Bs[16][136],
    int lane, int wm0, int wn0, float acc[4][4][4])
{
    const int g = lane >> 2, lq = lane & 3;
    #pragma unroll
    for (int ks = 0; ks < 16; ks += 8) {
        const int kb = ks + lq;
        uint32_t af[4][4], bf[4][2];
        #pragma unroll
        for (int mt = 0; mt < 4; mt++) {
            int m = wm0 + mt * 16 + g;
            af[mt][0] = As[kb][m];
            af[mt][1] = As[kb][m + 8];
            af[mt][2] = As[kb + 4][m];
            af[mt][3] = As[kb + 4][m + 8];
        }
        #pragma unroll
        for (int nt = 0; nt < 4; nt++) {
            int n = wn0 + nt * 8 + g;
            bf[nt][0] = Bs[kb][n];
            bf[nt][1] = Bs[kb + 4][n];
        }
        #pragma unroll
        for (int mt = 0; mt < 4; mt++)
            #pragma unroll
            for (int nt = 0; nt < 4; nt++)
                mma8(acc[mt][nt], af[mt], bf[nt]);
    }
}

__global__ __launch_bounds__(256, 2) void proj_kernel(
    const float* __restrict__ X, const float* __restrict__ W,
    const float* __restrict__ bias, float* __restrict__ Y)
{
    __shared__ uint32_t As[2][16][136];
    __shared__ uint32_t Bs[2][16][136];

    const int tid = threadIdx.x, lane = tid & 31, warp = tid >> 5;
    const int wm0 = (warp & 1) * 64, wn0 = (warp >> 1) * 32;
    const int row0 = blockIdx.y * 128, col0 = blockIdx.x * 128;
    const float* Ag = X + (size_t)row0 * DM;
    const float* Bg = W + (size_t)col0 * DM;

    float acc[4][4][4] = {};
    float4 ar[2], br[2];

    proj_stage_load(Ag, Bg, 0, tid, ar, br);
    proj_stage_store(As[0], Bs[0], tid, ar, br);
    __syncthreads();

    int buf = 0;
    for (int k0 = 16; k0 < DM; k0 += 16) {
        proj_stage_load(Ag, Bg, k0, tid, ar, br);     // prefetch next
        proj_tile_mma(As[buf], Bs[buf], lane, wm0, wn0, acc);
        proj_stage_store(As[buf ^ 1], Bs[buf ^ 1], tid, ar, br);
        __syncthreads();
        buf ^= 1;
    }
    proj_tile_mma(As[buf], Bs[buf], lane, wm0, wn0, acc);

    const int g = lane >> 2, lq = lane & 3;
    #pragma unroll
    for (int mt = 0; mt < 4; mt++) {
        int r = row0 + wm0 + mt * 16 + g;
        #pragma unroll
        for (int nt = 0; nt < 4; nt++) {
            int ccol = col0 + wn0 + nt * 8 + 2 * lq;
            float2 bv = *(const float2*)&bias[ccol];
            float2 o0 = { acc[mt][nt][0] + bv.x, acc[mt][nt][1] + bv.y };
            float2 o1 = { acc[mt][nt][2] + bv.x, acc[mt][nt][3] + bv.y };
            *(float2*)&Y[(size_t)r * DM + ccol]       = o0;
            *(float2*)&Y[(size_t)(r + 8) * DM + ccol] = o1;
        }
    }
}

// ===========================================================================
// scores_exp: P[z,q,k] = mask[k] * exp((Q.K^T)*scale)  (unnormalized),
// accumulating row sums into g_rowl via atomics.
// Whole K=64 depth staged once in smem -> no k-loop, one __syncthreads.
// grid = (16 key-blocks, 16 q-blocks, 24), 256 threads, warp layout 2x4.
// Dynamic smem: Qs[64][136] | Ks[64][136] = 69632 B.
// ===========================================================================
#define SMS_BYTES (2 * 64 * 136 * 4)

__global__ __launch_bounds__(256, 2) void scores_exp(
    const int* __restrict__ mask, float* __restrict__ P)
{
    extern __shared__ uint32_t sms[];
    uint32_t (*Qs)[136] = (uint32_t(*)[136])sms;
    uint32_t (*Ks)[136] = (uint32_t(*)[136])(sms + 64 * 136);

    const int tid = threadIdx.x, lane = tid & 31, warp = tid >> 5;
    const int g = lane >> 2, lq = lane & 3;
    const int wm0 = (warp & 1) * 64, wn0 = (warp >> 1) * 32;
    const int z = blockIdx.z, b = z / NH, h = z % NH;
    const int q0 = blockIdx.y * 128, c0 = blockIdx.x * 128;

    const float* Qg = g_q + (size_t)b * SEQ * DM + h * DHD;
    const float* Kg = g_k + (size_t)b * SEQ * DM + h * DHD;

    // Q tile 128x64 and K tile 128x64 -> smem transposed (tf32)
    #pragma unroll
    for (int t = 0; t < 8; t++) {
        int i = tid + t * 256;
        int r = i >> 4, c = (i & 15) * 4;
        float4 v = *(const float4*)(Qg + (size_t)(q0 + r) * DM + c);
        Qs[c + 0][r] = f2tf32(v.x);
        Qs[c + 1][r] = f2tf32(v.y);
        Qs[c + 2][r] = f2tf32(v.z);
        Qs[c + 3][r] = f2tf32(v.w);
        float4 w = *(const float4*)(Kg + (size_t)(c0 + r) * DM + c);
        Ks[c + 0][r] = f2tf32(w.x);
        Ks[c + 1][r] = f2tf32(w.y);
        Ks[c + 2][r] = f2tf32(w.z);
        Ks[c + 3][r] = f2tf32(w.w);
    }
    __syncthreads();

    float acc[4][4][4] = {};
    #pragma unroll
    for (int ks = 0; ks < 64; ks += 8) {
        const int kb = ks + lq;
        uint32_t af[4][4], bf[4][2];
        #pragma unroll
        for (int mt = 0; mt < 4; mt++) {
            int m = wm0 + mt * 16 + g;
            af[mt][0] = Qs[kb][m];
            af[mt][1] = Qs[kb][m + 8];
            af[mt][2] = Qs[kb + 4][m];
            af[mt][3] = Qs[kb + 4][m + 8];
        }
        #pragma unroll
        for (int nt = 0; nt < 4; nt++) {
            int n = wn0 + nt * 8 + g;
            bf[nt][0] = Ks[kb][n];
            bf[nt][1] = Ks[kb + 4][n];
        }
        #pragma unroll
        for (int mt = 0; mt < 4; mt++)
            #pragma unroll
            for (int nt = 0; nt < 4; nt++)
                mma8(acc[mt][nt], af[mt], bf[nt]);
    }

    // epilogue: p = mask * exp(s*scale); write; accumulate row sums
    const int* mrow = mask + b * SEQ;
    float* C = P + (size_t)z * SEQ * SEQ;
    float rs[4][2] = {};
    #pragma unroll
    for (int nt = 0; nt < 4; nt++) {
        int ccol = c0 + wn0 + nt * 8 + 2 * lq;
        float m0 = (mrow[ccol] != 0) ? 1.f : 0.f;
        float m1 = (mrow[ccol + 1] != 0) ? 1.f : 0.f;
        #pragma unroll
        for (int mt = 0; mt < 4; mt++) {
            int r = q0 + wm0 + mt * 16 + g;
            float p0 = m0 * __expf(acc[mt][nt][0] * ATT_SCALE);
            float p1 = m1 * __expf(acc[mt][nt][1] * ATT_SCALE);
            float p2 = m0 * __expf(acc[mt][nt][2] * ATT_SCALE);
            float p3 = m1 * __expf(acc[mt][nt][3] * ATT_SCALE);
            float2 w0 = { p0, p1 }, w1 = { p2, p3 };
            *(float2*)&C[(size_t)r * SEQ + ccol]       = w0;
            *(float2*)&C[(size_t)(r + 8) * SEQ + ccol] = w1;
            rs[mt][0] += p0 + p1;
            rs[mt][1] += p2 + p3;
        }
    }

    float* rl = g_rowl + (size_t)z * SEQ + q0;
    #pragma unroll
    for (int mt = 0; mt < 4; mt++)
        #pragma unroll
        for (int hh = 0; hh < 2; hh++) {
            float v = rs[mt][hh];
            v += __shfl_xor_sync(0xffffffffu, v, 1);
            v += __shfl_xor_sync(0xffffffffu, v, 2);
            if (lq == 0)
                atomicAdd(&rl[wm0 + mt * 16 + hh * 8 + g], v);
        }
}

// ===========================================================================
// pv_norm: reads unnormalized P, scales by 1/row_l during load,
// writes normalized probs back IN PLACE, accumulates O = Pn V -> g_attn.
// grid = (16 q-blocks, 24), 256 threads, warp layout 4x2 (warp tile 32x32).
// Register-prefetch pipelined over 64-key chunks.
// Dynamic smem: Ps[64][136] | Vs[64][72] | inv_l[128] = 53760 B.
// ===========================================================================
#define SMP_PS   0
#define SMP_VS   (64 * 136 * 4)
#define SMP_INV  (64 * 136 * 4 + 64 * 72 * 4)
#define SMP_BYTES (SMP_INV + 512)

__global__ __launch_bounds__(256, 2) void pv_norm(float* __restrict__ probs)
{
    extern __shared__ char smp[];
    uint32_t (*Ps)[136] = (uint32_t(*)[136])(smp + SMP_PS);
    uint32_t (*Vs)[72]  = (uint32_t(*)[72])(smp + SMP_VS);
    float* inv_l = (float*)(smp + SMP_INV);

    const int tid = threadIdx.x, lane = tid & 31, warp = tid >> 5;
    const int g = lane >> 2, lq = lane & 3;
    const int wm0 = (warp & 3) * 32, wn0 = (warp >> 2) * 32;
    const int z = blockIdx.y, b = z / NH, h = z % NH;
    const int q0 = blockIdx.x * 128;

    float* Pg = probs + (size_t)z * SEQ * SEQ + (size_t)q0 * SEQ;
    const float* Vg = g_v + (size_t)b * SEQ * DM + h * DHD;

    if (tid < 128)
        inv_l[tid] = 1.f / g_rowl[(size_t)z * SEQ + q0 + tid];
    __syncthreads();

    // per-thread load slots
    // P chunk: 128 rows x 64 cols = 2048 float4, 8/thread
    // V chunk: 64 rows x 64 cols  = 1024 float4, 4/thread
    float4 pr[8], vr[4];
    float  pinv[8];

    auto load_chunk = [&](int kb0) {
        #pragma unroll
        for (int t = 0; t < 8; t++) {
            int i = tid + t * 256;
            int r = i >> 4, c = (i & 15) * 4;
            float4 v = *(const float4*)(Pg + (size_t)r * SEQ + kb0 + c);
            float iv = inv_l[r];
            pr[t] = { v.x * iv, v.y * iv, v.z * iv, v.w * iv };
            pinv[t] = 1.f;   // placeholder (kept for reg symmetry)
        }
        #pragma unroll
        for (int t = 0; t < 4; t++) {
            int i = tid + t * 256;
            int n = i >> 4, c = (i & 15) * 4;
            vr[t] = *(const float4*)(Vg + (size_t)(kb0 + n) * DM + c);
        }
    };

    auto store_chunk = [&](int kb0) {
        #pragma unroll
        for (int t = 0; t < 8; t++) {
            int i = tid + t * 256;
            int r = i >> 4, c = (i & 15) * 4;
            // write normalized probs back
            *(float4*)(Pg + (size_t)r * SEQ + kb0 + c) = pr[t];
            Ps[c + 0][r] = f2tf32(pr[t].x);
            Ps[c + 1][r] = f2tf32(pr[t].y);
            Ps[c + 2][r] = f2tf32(pr[t].z);
            Ps[c + 3][r] = f2tf32(pr[t].w);
        }
        #pragma unroll
        for (int t = 0; t < 4; t++) {
            int i = tid + t * 256;
            int n = i >> 4, c = (i & 15) * 4;
            Vs[n][c + 0] = f2tf32(vr[t].x);
            Vs[n][c + 1] = f2tf32(vr[t].y);
            Vs[n][c + 2] = f2tf32(vr[t].z);
            Vs[n][c + 3] = f2tf32(vr[t].w);
        }
    };

    float oacc[2][4][4] = {};

    auto chunk_mma = [&]() {
        #pragma unroll
        for (int ks = 0; ks < 64; ks += 8) {
            const int kb = ks + lq;
            uint32_t af[2][4], bf[4][2];
            #pragma unroll
            for (int mt = 0; mt < 2; mt++) {
                int m = wm0 + mt * 16 + g;
                af[mt][0] = Ps[kb][m];
                af[mt][1] = Ps[kb][m + 8];
                af[mt][2] = Ps[kb + 4][m];
                af[mt][3] = Ps[kb + 4][m + 8];
            }
            #pragma unroll
            for (int nt = 0; nt < 4; nt++) {
                int n = wn0 + nt * 8 + g;
                bf[nt][0] = Vs[kb][n];
                bf[nt][1] = Vs[kb + 4][n];
            }
            #pragma unroll
            for (int mt = 0; mt < 2; mt++)
                #pragma unroll
                for (int nt = 0; nt < 4; nt++)
                    mma8(oacc[mt][nt], af[mt], bf[nt]);
        }
    };

    load_chunk(0);
    store_chunk(0);
    __syncthreads();

    for (int kb0 = 64; kb0 < SEQ; kb0 += 64) {
        load_chunk(kb0);          // prefetch next chunk into registers
        chunk_mma();              // consume current smem
        __syncthreads();          // all reads done before overwrite
        store_chunk(kb0);
        __syncthreads();
    }
    chunk_mma();

    // O -> g_attn
    float* Og = g_attn + (size_t)b * SEQ * DM + h * DHD + (size_t)q0 * DM;
    #pragma unroll
    for (int mt = 0; mt < 2; mt++) {
        int r = wm0 + mt * 16 + g;
        #pragma unroll
        for (int nt = 0; nt < 4; nt++) {
            int c = wn0 + nt * 8 + 2 * lq;
            float2 o0 = { oacc[mt][nt][0], oacc[mt][nt][1] };
            float2 o1 = { oacc[mt][nt][2], oacc[mt][nt][3] };
            *(float2*)&Og[(size_t)r * DM + c]       = o0;
            *(float2*)&Og[(size_t)(r + 8) * DM + c] = o1;
        }
    }
}

// ---------------------------------------------------------------------------
extern "C" void kernel_launch(void* const* d_in, const int* in_sizes, int n_in,
                              void* d_out, int out_size)
{
    const float* query = (const float*)d_in[0];
    const float* key   = (const float*)d_in[1];
    const float* value = (const float*)d_in[2];
    const int*   mask  = (const int*)d_in[3];
    const float* wq = (const float*)d_in[4];
    const float* bq = (const float*)d_in[5];
    const float* wk = (const float*)d_in[6];
    const float* bk = (const float*)d_in[7];
    const float* wv = (const float*)d_in[8];
    const float* bv = (const float*)d_in[9];
    const float* wo = (const float*)d_in[10];
    const float* bo = (const float*)d_in[11];

    float* out   = (float*)d_out;                       // [B, S, D]
    float* probs = out + (size_t)BATCH * SEQ * DM;      // [B, H, S, S]

    float *qp, *kp, *vp, *ap;
    cudaGetSymbolAddress((void**)&qp, g_q);
    cudaGetSymbolAddress((void**)&kp, g_k);
    cudaGetSymbolAddress((void**)&vp, g_v);
    cudaGetSymbolAddress((void**)&ap, g_attn);

    cudaFuncSetAttribute(scores_exp,
                         cudaFuncAttributeMaxDynamicSharedMemorySize, SMS_BYTES);
    cudaFuncSetAttribute(pv_norm,
                         cudaFuncAttributeMaxDynamicSharedMemorySize, SMP_BYTES);

    init_rowl<<<BATCH * NH * SEQ / 256, 256>>>();

    dim3 proj_grid(DM / 128, (BATCH * SEQ) / 128);      // (6, 32)
    proj_kernel<<<proj_grid, 256>>>(query, wq, bq, qp);
    proj_kernel<<<proj_grid, 256>>>(key,   wk, bk, kp);
    proj_kernel<<<proj_grid, 256>>>(value, wv, bv, vp);

    dim3 sc_grid(SEQ / 128, SEQ / 128, BATCH * NH);     // (16, 16, 24)
    scores_exp<<<sc_grid, 256, SMS_BYTES>>>(mask, probs);

    dim3 pv_grid(SEQ / 128, BATCH * NH);                // (16, 24)
    pv_norm<<<pv_grid, 256, SMP_BYTES>>>(probs);

    proj_kernel<<<proj_grid, 256>>>(ap, wo, bo, out);
}

// round 5
// speedup vs baseline: 1.0884x; 1.0884x over previous
#include <cuda_runtime.h>
#include <cstdint>
#include <cstddef>

// Problem constants
#define BATCH 2
#define SEQ   2048
#define DM    768
#define NH    12
#define DHD   64
#define ATT_SCALE 0.125f   // 1/sqrt(64)
#define KSPLIT 4
#define KEYS_PER_SPLIT (SEQ / KSPLIT)   // 512

// Scratch (allocation-free rule: __device__ globals)
__device__ float g_q[BATCH * SEQ * DM];
__device__ float g_k[BATCH * SEQ * DM];
__device__ float g_v[BATCH * SEQ * DM];
__device__ float g_attn[BATCH * SEQ * DM];
__device__ float g_rowl[BATCH * NH * SEQ];   // softmax row sums

// ---------------------------------------------------------------------------
// tf32 helpers
// ---------------------------------------------------------------------------
__device__ __forceinline__ uint32_t f2tf32(float f) {
    uint32_t u;
    asm("cvt.rna.tf32.f32 %0, %1;" : "=r"(u) : "f"(f));
    return u;
}

__device__ __forceinline__ void mma8(float* c, const uint32_t* a, const uint32_t* b) {
    asm volatile(
        "mma.sync.aligned.m16n8k8.row.col.f32.tf32.tf32.f32 "
        "{%0,%1,%2,%3},{%4,%5,%6,%7},{%8,%9},{%0,%1,%2,%3};"
        : "+f"(c[0]), "+f"(c[1]), "+f"(c[2]), "+f"(c[3])
        : "r"(a[0]), "r"(a[1]), "r"(a[2]), "r"(a[3]), "r"(b[0]), "r"(b[1]));
}

// ===========================================================================
// init: zero row sums and O accumulator
// ===========================================================================
__global__ void init_zero()
{
    int i = blockIdx.x * 256 + threadIdx.x;
    if (i < BATCH * NH * SEQ) g_rowl[i] = 0.f;
    if (i < BATCH * SEQ * DM) g_attn[i] = 0.f;
}

// ===========================================================================
// GEMM core for projections: 128x128 CTA tile, BK=16, double-buffered.
// 256 threads (8 warps, 2x4; warp tile 64x32).
// ===========================================================================
__device__ __forceinline__ void proj_stage_load(
    const float* __restrict__ Ag, const float* __restrict__ Bg,
    int k0, int tid, float4 ar[2], float4 br[2])
{
    #pragma unroll
    for (int t = 0; t < 2; t++) {
        int i = tid + t * 256;
        ar[t] = *(const float4*)(Ag + (size_t)(i >> 2) * DM + k0 + (i & 3) * 4);
    }
    #pragma unroll
    for (int t = 0; t < 2; t++) {
        int i = tid + t * 256;
        br[t] = *(const float4*)(Bg + (size_t)(i >> 2) * DM + k0 + (i & 3) * 4);
    }
}

__device__ __forceinline__ void proj_stage_store(
    uint32_t As[16][136], uint32_t Bs[16][136],
    int tid, const float4 ar[2], const float4 br[2])
{
    #pragma unroll
    for (int t = 0; t < 2; t++) {
        int i = tid + t * 256;
        int r = i >> 2, c = (i & 3) * 4;
        As[c + 0][r] = f2tf32(ar[t].x);
        As[c + 1][r] = f2tf32(ar[t].y);
        As[c + 2][r] = f2tf32(ar[t].z);
        As[c + 3][r] = f2tf32(ar[t].w);
    }
    #pragma unroll
    for (int t = 0; t < 2; t++) {
        int i = tid + t * 256;
        int r = i >> 2, c = (i & 3) * 4;
        Bs[c + 0][r] = f2tf32(br[t].x);
        Bs[c + 1][r] = f2tf32(br[t].y);
        Bs[c + 2][r] = f2tf32(br[t].z);
        Bs[c + 3][r] = f2tf32(br[t].w);
    }
}

__device__ __forceinline__ void proj_tile_mma(
    const uint32_t As[16][136], const uint32_t Bs[16][136],
    int lane, int wm0, int wn0, float acc[4][4][4])
{
    const int g = lane >> 2, lq = lane & 3;
    #pragma unroll
    for (int ks = 0; ks < 16; ks += 8) {
        const int kb = ks + lq;
        uint32_t af[4][4], bf[4][2];
        #pragma unroll
        for (int mt = 0; mt < 4; mt++) {
            int m = wm0 + mt * 16 + g;
            af[mt][0] = As[kb][m];
            af[mt][1] = As[kb][m + 8];
            af[mt][2] = As[kb + 4][m];
            af[mt][3] = As[kb + 4][m + 8];
        }
        #pragma unroll
        for (int nt = 0; nt < 4; nt++) {
            int n = wn0 + nt * 8 + g;
            bf[nt][0] = Bs[kb][n];
            bf[nt][1] = Bs[kb + 4][n];
        }
        #pragma unroll
        for (int mt = 0; mt < 4; mt++)
            #pragma unroll
            for (int nt = 0; nt < 4; nt++)
                mma8(acc[mt][nt], af[mt], bf[nt]);
    }
}

__device__ __forceinline__ void proj_body(
    const float* __restrict__ X, const float* __restrict__ W,
    const float* __restrict__ bias, float* __restrict__ Y,
    int row0, int col0)
{
    __shared__ uint32_t As[2][16][136];
    __shared__ uint32_t Bs[2][16][136];

    const int tid = threadIdx.x, lane = tid & 31, warp = tid >> 5;
    const int wm0 = (warp & 1) * 64, wn0 = (warp >> 1) * 32;
    const float* Ag = X + (size_t)row0 * DM;
    const float* Bg = W + (size_t)col0 * DM;

    float acc[4][4][4] = {};
    float4 ar[2], br[2];

    proj_stage_load(Ag, Bg, 0, tid, ar, br);
    proj_stage_store(As[0], Bs[0], tid, ar, br);
    __syncthreads();

    int buf = 0;
    for (int k0 = 16; k0 < DM; k0 += 16) {
        proj_stage_load(Ag, Bg, k0, tid, ar, br);
        proj_tile_mma(As[buf], Bs[buf], lane, wm0, wn0, acc);
        proj_stage_store(As[buf ^ 1], Bs[buf ^ 1], tid, ar, br);
        __syncthreads();
        buf ^= 1;
    }
    proj_tile_mma(As[buf], Bs[buf], lane, wm0, wn0, acc);

    const int g = lane >> 2, lq = lane & 3;
    #pragma unroll
    for (int mt = 0; mt < 4; mt++) {
        int r = row0 + wm0 + mt * 16 + g;
        #pragma unroll
        for (int nt = 0; nt < 4; nt++) {
            int ccol = col0 + wn0 + nt * 8 + 2 * lq;
            float2 bv = *(const float2*)&bias[ccol];
            float2 o0 = { acc[mt][nt][0] + bv.x, acc[mt][nt][1] + bv.y };
            float2 o1 = { acc[mt][nt][2] + bv.x, acc[mt][nt][3] + bv.y };
            *(float2*)&Y[(size_t)r * DM + ccol]       = o0;
            *(float2*)&Y[(size_t)(r + 8) * DM + ccol] = o1;
        }
    }
}

// Merged QKV projection: blockIdx.z selects which projection.
__global__ __launch_bounds__(256, 2) void qkv_proj(
    const float* __restrict__ q,  const float* __restrict__ k,
    const float* __restrict__ v,
    const float* __restrict__ wq, const float* __restrict__ bq,
    const float* __restrict__ wk, const float* __restrict__ bk,
    const float* __restrict__ wv, const float* __restrict__ bv)
{
    const int z = blockIdx.z;
    const float* X = (z == 0) ? q  : (z == 1) ? k  : v;
    const float* W = (z == 0) ? wq : (z == 1) ? wk : wv;
    const float* B = (z == 0) ? bq : (z == 1) ? bk : bv;
    float*       Y = (z == 0) ? g_q : (z == 1) ? g_k : g_v;
    proj_body(X, W, B, Y, blockIdx.y * 128, blockIdx.x * 128);
}

// Output projection.
__global__ __launch_bounds__(256, 2) void o_proj(
    const float* __restrict__ W, const float* __restrict__ bias,
    float* __restrict__ Y)
{
    proj_body(g_attn, W, bias, Y, blockIdx.y * 128, blockIdx.x * 128);
}

// ===========================================================================
// scores_exp: P[z,q,k] = mask[k] * exp((Q.K^T)*scale)  (UNNORMALIZED),
// accumulating row sums into g_rowl (smem pre-reduced, 1 atomic/row/CTA).
// grid = (16 key-blocks, 16 q-blocks, 24), 256 threads, warp layout 2x4.
// Dynamic smem: Qs[64][136] | Ks[64][136] = 69632 B.
// ===========================================================================
#define SMS_BYTES (2 * 64 * 136 * 4)

__global__ __launch_bounds__(256, 2) void scores_exp(
    const int* __restrict__ mask, float* __restrict__ P)
{
    extern __shared__ uint32_t sms[];
    uint32_t (*Qs)[136] = (uint32_t(*)[136])sms;
    uint32_t (*Ks)[136] = (uint32_t(*)[136])(sms + 64 * 136);
    __shared__ float srow[128];

    const int tid = threadIdx.x, lane = tid & 31, warp = tid >> 5;
    const int g = lane >> 2, lq = lane & 3;
    const int wm0 = (warp & 1) * 64, wn0 = (warp >> 1) * 32;
    const int z = blockIdx.z, b = z / NH, h = z % NH;
    const int q0 = blockIdx.y * 128, c0 = blockIdx.x * 128;

    const float* Qg = g_q + (size_t)b * SEQ * DM + h * DHD;
    const float* Kg = g_k + (size_t)b * SEQ * DM + h * DHD;

    if (tid < 128) srow[tid] = 0.f;

    #pragma unroll
    for (int t = 0; t < 8; t++) {
        int i = tid + t * 256;
        int r = i >> 4, c = (i & 15) * 4;
        float4 v = *(const float4*)(Qg + (size_t)(q0 + r) * DM + c);
        Qs[c + 0][r] = f2tf32(v.x);
        Qs[c + 1][r] = f2tf32(v.y);
        Qs[c + 2][r] = f2tf32(v.z);
        Qs[c + 3][r] = f2tf32(v.w);
        float4 w = *(const float4*)(Kg + (size_t)(c0 + r) * DM + c);
        Ks[c + 0][r] = f2tf32(w.x);
        Ks[c + 1][r] = f2tf32(w.y);
        Ks[c + 2][r] = f2tf32(w.z);
        Ks[c + 3][r] = f2tf32(w.w);
    }
    __syncthreads();

    float acc[4][4][4] = {};
    #pragma unroll
    for (int ks = 0; ks < 64; ks += 8) {
        const int kb = ks + lq;
        uint32_t af[4][4], bf[4][2];
        #pragma unroll
        for (int mt = 0; mt < 4; mt++) {
            int m = wm0 + mt * 16 + g;
            af[mt][0] = Qs[kb][m];
            af[mt][1] = Qs[kb][m + 8];
            af[mt][2] = Qs[kb + 4][m];
            af[mt][3] = Qs[kb + 4][m + 8];
        }
        #pragma unroll
        for (int nt = 0; nt < 4; nt++) {
            int n = wn0 + nt * 8 + g;
            bf[nt][0] = Ks[kb][n];
            bf[nt][1] = Ks[kb + 4][n];
        }
        #pragma unroll
        for (int mt = 0; mt < 4; mt++)
            #pragma unroll
            for (int nt = 0; nt < 4; nt++)
                mma8(acc[mt][nt], af[mt], bf[nt]);
    }

    const int* mrow = mask + b * SEQ;
    float* C = P + (size_t)z * SEQ * SEQ;
    float rs[4][2] = {};
    #pragma unroll
    for (int nt = 0; nt < 4; nt++) {
        int ccol = c0 + wn0 + nt * 8 + 2 * lq;
        float m0 = (mrow[ccol] != 0) ? 1.f : 0.f;
        float m1 = (mrow[ccol + 1] != 0) ? 1.f : 0.f;
        #pragma unroll
        for (int mt = 0; mt < 4; mt++) {
            int r = q0 + wm0 + mt * 16 + g;
            float p0 = m0 * __expf(acc[mt][nt][0] * ATT_SCALE);
            float p1 = m1 * __expf(acc[mt][nt][1] * ATT_SCALE);
            float p2 = m0 * __expf(acc[mt][nt][2] * ATT_SCALE);
            float p3 = m1 * __expf(acc[mt][nt][3] * ATT_SCALE);
            float2 w0 = { p0, p1 }, w1 = { p2, p3 };
            *(float2*)&C[(size_t)r * SEQ + ccol]       = w0;
            *(float2*)&C[(size_t)(r + 8) * SEQ + ccol] = w1;
            rs[mt][0] += p0 + p1;
            rs[mt][1] += p2 + p3;
        }
    }

    // reduce row sums: shuffle within quad-group, then smem, then 1 global/row
    #pragma unroll
    for (int mt = 0; mt < 4; mt++)
        #pragma unroll
        for (int hh = 0; hh < 2; hh++) {
            float v = rs[mt][hh];
            v += __shfl_xor_sync(0xffffffffu, v, 1);
            v += __shfl_xor_sync(0xffffffffu, v, 2);
            if (lq == 0)
                atomicAdd(&srow[wm0 + mt * 16 + hh * 8 + g], v);
        }
    __syncthreads();
    if (tid < 128)
        atomicAdd(&g_rowl[(size_t)z * SEQ + q0 + tid], srow[tid]);
}

// ===========================================================================
// pv_norm: reads unnormalized P, writes normalized probs IN PLACE,
// O_partial = Pn V accumulated over 512 keys, atomicAdd into g_attn.
// grid = (16 q-blocks, KSPLIT=4, 24) = 1536 CTAs; 256 thr; warps 4x2.
// Double-buffered smem; one __syncthreads per 64-key chunk.
// Dynamic smem: Ps[2][64][136] | Vs[2][64][72] | inv_l[128] = 107008 B.
// ===========================================================================
#define SMP_PS   0
#define SMP_VS   (2 * 64 * 136 * 4)
#define SMP_INV  (SMP_VS + 2 * 64 * 72 * 4)
#define SMP_BYTES (SMP_INV + 512)

__global__ __launch_bounds__(256, 2) void pv_norm(float* __restrict__ probs)
{
    extern __shared__ char smp[];
    uint32_t (*Ps)[64][136] = (uint32_t(*)[64][136])(smp + SMP_PS);
    uint32_t (*Vs)[64][72]  = (uint32_t(*)[64][72])(smp + SMP_VS);
    float* inv_l = (float*)(smp + SMP_INV);

    const int tid = threadIdx.x, lane = tid & 31, warp = tid >> 5;
    const int g = lane >> 2, lq = lane & 3;
    const int wm0 = (warp & 3) * 32, wn0 = (warp >> 2) * 32;
    const int z = blockIdx.z, b = z / NH, h = z % NH;
    const int q0 = blockIdx.x * 128;
    const int k_base = blockIdx.y * KEYS_PER_SPLIT;

    float* Pg = probs + (size_t)z * SEQ * SEQ + (size_t)q0 * SEQ;
    const float* Vg = g_v + (size_t)b * SEQ * DM + h * DHD;

    if (tid < 128)
        inv_l[tid] = 1.f / g_rowl[(size_t)z * SEQ + q0 + tid];
    __syncthreads();

    float4 pr[8], vr[4];

    auto load_chunk = [&](int kb0) {
        #pragma unroll
        for (int t = 0; t < 8; t++) {
            int i = tid + t * 256;
            int r = i >> 4, c = (i & 15) * 4;
            pr[t] = *(const float4*)(Pg + (size_t)r * SEQ + kb0 + c);
        }
        #pragma unroll
        for (int t = 0; t < 4; t++) {
            int i = tid + t * 256;
            int n = i >> 4, c = (i & 15) * 4;
            vr[t] = *(const float4*)(Vg + (size_t)(kb0 + n) * DM + c);
        }
    };

    auto store_chunk = [&](int kb0, int buf) {
        #pragma unroll
        for (int t = 0; t < 8; t++) {
            int i = tid + t * 256;
            int r = i >> 4, c = (i & 15) * 4;
            float iv = inv_l[r];
            float4 w = { pr[t].x * iv, pr[t].y * iv, pr[t].z * iv, pr[t].w * iv };
            *(float4*)(Pg + (size_t)r * SEQ + kb0 + c) = w;   // normalized probs
            Ps[buf][c + 0][r] = f2tf32(w.x);
            Ps[buf][c + 1][r] = f2tf32(w.y);
            Ps[buf][c + 2][r] = f2tf32(w.z);
            Ps[buf][c + 3][r] = f2tf32(w.w);
        }
        #pragma unroll
        for (int t = 0; t < 4; t++) {
            int i = tid + t * 256;
            int n = i >> 4, c = (i & 15) * 4;
            Vs[buf][n][c + 0] = f2tf32(vr[t].x);
            Vs[buf][n][c + 1] = f2tf32(vr[t].y);
            Vs[buf][n][c + 2] = f2tf32(vr[t].z);
            Vs[buf][n][c + 3] = f2tf32(vr[t].w);
        }
    };

    float oacc[2][4][4] = {};

    auto chunk_mma = [&](int buf) {
        #pragma unroll
        for (int ks = 0; ks < 64; ks += 8) {
            const int kb = ks + lq;
            uint32_t af[2][4], bf[4][2];
            #pragma unroll
            for (int mt = 0; mt < 2; mt++) {
                int m = wm0 + mt * 16 + g;
                af[mt][0] = Ps[buf][kb][m];
                af[mt][1] = Ps[buf][kb][m + 8];
                af[mt][2] = Ps[buf][kb + 4][m];
                af[mt][3] = Ps[buf][kb + 4][m + 8];
            }
            #pragma unroll
            for (int nt = 0; nt < 4; nt++) {
                int n = wn0 + nt * 8 + g;
                bf[nt][0] = Vs[buf][kb][n];
                bf[nt][1] = Vs[buf][kb + 4][n];
            }
            #pragma unroll
            for (int mt = 0; mt < 2; mt++)
                #pragma unroll
                for (int nt = 0; nt < 4; nt++)
                    mma8(oacc[mt][nt], af[mt], bf[nt]);
        }
    };

    load_chunk(k_base);
    store_chunk(k_base, 0);
    __syncthreads();

    int buf = 0;
    for (int c = 1; c < KEYS_PER_SPLIT / 64; c++) {
        load_chunk(k_base + c * 64);       // LDGs in flight during mma
        chunk_mma(buf);
        store_chunk(k_base + c * 64, buf ^ 1);
        __syncthreads();
        buf ^= 1;
    }
    chunk_mma(buf);

    // partial O -> atomic accumulate
    float* Og = g_attn + (size_t)b * SEQ * DM + h * DHD + (size_t)q0 * DM;
    #pragma unroll
    for (int mt = 0; mt < 2; mt++) {
        int r = wm0 + mt * 16 + g;
        #pragma unroll
        for (int nt = 0; nt < 4; nt++) {
            int c = wn0 + nt * 8 + 2 * lq;
            atomicAdd(&Og[(size_t)r * DM + c],           oacc[mt][nt][0]);
            atomicAdd(&Og[(size_t)r * DM + c + 1],       oacc[mt][nt][1]);
            atomicAdd(&Og[(size_t)(r + 8) * DM + c],     oacc[mt][nt][2]);
            atomicAdd(&Og[(size_t)(r + 8) * DM + c + 1], oacc[mt][nt][3]);
        }
    }
}

// ---------------------------------------------------------------------------
extern "C" void kernel_launch(void* const* d_in, const int* in_sizes, int n_in,
                              void* d_out, int out_size)
{
    const float* query = (const float*)d_in[0];
    const float* key   = (const float*)d_in[1];
    const float* value = (const float*)d_in[2];
    const int*   mask  = (const int*)d_in[3];
    const float* wq = (const float*)d_in[4];
    const float* bq = (const float*)d_in[5];
    const float* wk = (const float*)d_in[6];
    const float* bk = (const float*)d_in[7];
    const float* wv = (const float*)d_in[8];
    const float* bv = (const float*)d_in[9];
    const float* wo = (const float*)d_in[10];
    const float* bo = (const float*)d_in[11];

    float* out   = (float*)d_out;                       // [B, S, D]
    float* probs = out + (size_t)BATCH * SEQ * DM;      // [B, H, S, S]

    cudaFuncSetAttribute(scores_exp,
                         cudaFuncAttributeMaxDynamicSharedMemorySize, SMS_BYTES);
    cudaFuncSetAttribute(pv_norm,
                         cudaFuncAttributeMaxDynamicSharedMemorySize, SMP_BYTES);

    init_zero<<<(BATCH * SEQ * DM + 255) / 256, 256>>>();

    dim3 qkv_grid(DM / 128, (BATCH * SEQ) / 128, 3);    // (6, 32, 3)
    qkv_proj<<<qkv_grid, 256>>>(query, key, value,
                                wq, bq, wk, bk, wv, bv);

    dim3 sc_grid(SEQ / 128, SEQ / 128, BATCH * NH);     // (16, 16, 24)
    scores_exp<<<sc_grid, 256, SMS_BYTES>>>(mask, probs);

    dim3 pv_grid(SEQ / 128, KSPLIT, BATCH * NH);        // (16, 4, 24)
    pv_norm<<<pv_grid, 256, SMP_BYTES>>>(probs);

    dim3 o_grid(DM / 128, (BATCH * SEQ) / 128);         // (6, 32)
    o_proj<<<o_grid, 256>>>(wo, bo, out);
}

// round 6
// speedup vs baseline: 1.2690x; 1.1659x over previous
#include <cuda_runtime.h>
#include <cstdint>
#include <cstddef>

// Problem constants
#define BATCH 2
#define SEQ   2048
#define DM    768
#define NH    12
#define DHD   64
#define ATT_SCALE 0.125f   // 1/sqrt(64)
#define KSPLIT 4
#define KEYS_PER_SPLIT (SEQ / KSPLIT)   // 512

// Scratch (allocation-free rule: __device__ globals)
__device__ float g_q[BATCH * SEQ * DM];
__device__ float g_k[BATCH * SEQ * DM];
__device__ float g_v[BATCH * SEQ * DM];
__device__ float g_attn[BATCH * SEQ * DM];
__device__ float g_rowl[BATCH * NH * SEQ];   // softmax row sums

// ---------------------------------------------------------------------------
// helpers
// ---------------------------------------------------------------------------
__device__ __forceinline__ uint32_t f2tf32(float f) {
    uint32_t u;
    asm("cvt.rna.tf32.f32 %0, %1;" : "=r"(u) : "f"(f));
    return u;
}

__device__ __forceinline__ void mma8(float* c, const uint32_t* a, const uint32_t* b) {
    asm volatile(
        "mma.sync.aligned.m16n8k8.row.col.f32.tf32.tf32.f32 "
        "{%0,%1,%2,%3},{%4,%5,%6,%7},{%8,%9},{%0,%1,%2,%3};"
        : "+f"(c[0]), "+f"(c[1]), "+f"(c[2]), "+f"(c[3])
        : "r"(a[0]), "r"(a[1]), "r"(a[2]), "r"(a[3]), "r"(b[0]), "r"(b[1]));
}

__device__ __forceinline__ uint32_t smem_u32(const void* p) {
    uint32_t a;
    asm("{ .reg .u64 t; cvta.to.shared.u64 t, %1; cvt.u32.u64 %0, t; }"
        : "=r"(a) : "l"(p));
    return a;
}

__device__ __forceinline__ void cp16(uint32_t dst, const void* src) {
    asm volatile("cp.async.cg.shared.global [%0], [%1], 16;" :: "r"(dst), "l"(src));
}
__device__ __forceinline__ void cp_commit() {
    asm volatile("cp.async.commit_group;");
}
template <int N>
__device__ __forceinline__ void cp_wait() {
    asm volatile("cp.async.wait_group %0;" :: "n"(N));
}

// ===========================================================================
// init: zero row sums and O accumulator
// ===========================================================================
__global__ void init_zero()
{
    int i = blockIdx.x * 256 + threadIdx.x;
    if (i < BATCH * NH * SEQ) g_rowl[i] = 0.f;
    if (i < BATCH * SEQ * DM) g_attn[i] = 0.f;
}

// ===========================================================================
// Projection core: 64x128 CTA tile, BK=16, double-buffered.
// 256 threads (8 warps 2x4; warp tile 32x32).
// ===========================================================================
__device__ __forceinline__ void proj_body(
    const float* __restrict__ X, const float* __restrict__ W,
    const float* __restrict__ bias, float* __restrict__ Y,
    int row0, int col0)
{
    __shared__ uint32_t As[2][16][72];
    __shared__ uint32_t Bs[2][16][136];

    const int tid = threadIdx.x, lane = tid & 31, warp = tid >> 5;
    const int g = lane >> 2, lq = lane & 3;
    const int wm0 = (warp & 1) * 32, wn0 = (warp >> 1) * 32;
    const float* Ag = X + (size_t)row0 * DM;
    const float* Bg = W + (size_t)col0 * DM;

    float acc[2][4][4] = {};
    float4 ar, br[2];

    auto stage_load = [&](int k0) {
        int rA = tid >> 2, cA = (tid & 3) * 4;
        ar = *(const float4*)(Ag + (size_t)rA * DM + k0 + cA);
        #pragma unroll
        for (int t = 0; t < 2; t++) {
            int i = tid + t * 256;
            br[t] = *(const float4*)(Bg + (size_t)(i >> 2) * DM + k0 + (i & 3) * 4);
        }
    };
    auto stage_store = [&](uint32_t A_[16][72], uint32_t B_[16][136]) {
        int rA = tid >> 2, cA = (tid & 3) * 4;
        A_[cA + 0][rA] = f2tf32(ar.x);
        A_[cA + 1][rA] = f2tf32(ar.y);
        A_[cA + 2][rA] = f2tf32(ar.z);
        A_[cA + 3][rA] = f2tf32(ar.w);
        #pragma unroll
        for (int t = 0; t < 2; t++) {
            int i = tid + t * 256;
            int r = i >> 2, c = (i & 3) * 4;
            B_[c + 0][r] = f2tf32(br[t].x);
            B_[c + 1][r] = f2tf32(br[t].y);
            B_[c + 2][r] = f2tf32(br[t].z);
            B_[c + 3][r] = f2tf32(br[t].w);
        }
    };
    auto tile_mma = [&](const uint32_t A_[16][72], const uint32_t B_[16][136]) {
        #pragma unroll
        for (int ks = 0; ks < 16; ks += 8) {
            const int kb = ks + lq;
            uint32_t af[2][4], bf[4][2];
            #pragma unroll
            for (int mt = 0; mt < 2; mt++) {
                int m = wm0 + mt * 16 + g;
                af[mt][0] = A_[kb][m];
                af[mt][1] = A_[kb][m + 8];
                af[mt][2] = A_[kb + 4][m];
                af[mt][3] = A_[kb + 4][m + 8];
            }
            #pragma unroll
            for (int nt = 0; nt < 4; nt++) {
                int n = wn0 + nt * 8 + g;
                bf[nt][0] = B_[kb][n];
                bf[nt][1] = B_[kb + 4][n];
            }
            #pragma unroll
            for (int mt = 0; mt < 2; mt++)
                #pragma unroll
                for (int nt = 0; nt < 4; nt++)
                    mma8(acc[mt][nt], af[mt], bf[nt]);
        }
    };

    stage_load(0);
    stage_store(As[0], Bs[0]);
    __syncthreads();

    int buf = 0;
    for (int k0 = 16; k0 < DM; k0 += 16) {
        stage_load(k0);
        tile_mma(As[buf], Bs[buf]);
        stage_store(As[buf ^ 1], Bs[buf ^ 1]);
        __syncthreads();
        buf ^= 1;
    }
    tile_mma(As[buf], Bs[buf]);

    #pragma unroll
    for (int mt = 0; mt < 2; mt++) {
        int r = row0 + wm0 + mt * 16 + g;
        #pragma unroll
        for (int nt = 0; nt < 4; nt++) {
            int ccol = col0 + wn0 + nt * 8 + 2 * lq;
            float2 bv = *(const float2*)&bias[ccol];
            float2 o0 = { acc[mt][nt][0] + bv.x, acc[mt][nt][1] + bv.y };
            float2 o1 = { acc[mt][nt][2] + bv.x, acc[mt][nt][3] + bv.y };
            *(float2*)&Y[(size_t)r * DM + ccol]       = o0;
            *(float2*)&Y[(size_t)(r + 8) * DM + ccol] = o1;
        }
    }
}

__global__ __launch_bounds__(256, 3) void qkv_proj(
    const float* __restrict__ q,  const float* __restrict__ k,
    const float* __restrict__ v,
    const float* __restrict__ wq, const float* __restrict__ bq,
    const float* __restrict__ wk, const float* __restrict__ bk,
    const float* __restrict__ wv, const float* __restrict__ bv)
{
    const int z = blockIdx.z;
    const float* X = (z == 0) ? q  : (z == 1) ? k  : v;
    const float* W = (z == 0) ? wq : (z == 1) ? wk : wv;
    const float* B = (z == 0) ? bq : (z == 1) ? bk : bv;
    float*       Y = (z == 0) ? g_q : (z == 1) ? g_k : g_v;
    proj_body(X, W, B, Y, blockIdx.y * 64, blockIdx.x * 128);
}

__global__ __launch_bounds__(256, 3) void o_proj(
    const float* __restrict__ W, const float* __restrict__ bias,
    float* __restrict__ Y)
{
    proj_body(g_attn, W, bias, Y, blockIdx.y * 64, blockIdx.x * 128);
}

// ===========================================================================
// scores_exp: P[z,q,k] = mask[k] * exp((Q.K^T)*scale)  (UNNORMALIZED),
// rowsums into g_rowl (smem pre-reduced, 1 atomic/row/CTA).
// grid = (16, 16, 24), 256 threads, warp layout 2x4.
// ===========================================================================
#define SMS_BYTES (2 * 64 * 136 * 4)

__global__ __launch_bounds__(256, 2) void scores_exp(
    const int* __restrict__ mask, float* __restrict__ P)
{
    extern __shared__ uint32_t sms[];
    uint32_t (*Qs)[136] = (uint32_t(*)[136])sms;
    uint32_t (*Ks)[136] = (uint32_t(*)[136])(sms + 64 * 136);
    __shared__ float srow[128];

    const int tid = threadIdx.x, lane = tid & 31, warp = tid >> 5;
    const int g = lane >> 2, lq = lane & 3;
    const int wm0 = (warp & 1) * 64, wn0 = (warp >> 1) * 32;
    const int z = blockIdx.z, b = z / NH, h = z % NH;
    const int q0 = blockIdx.y * 128, c0 = blockIdx.x * 128;

    const float* Qg = g_q + (size_t)b * SEQ * DM + h * DHD;
    const float* Kg = g_k + (size_t)b * SEQ * DM + h * DHD;

    if (tid < 128) srow[tid] = 0.f;

    #pragma unroll
    for (int t = 0; t < 8; t++) {
        int i = tid + t * 256;
        int r = i >> 4, c = (i & 15) * 4;
        float4 v = *(const float4*)(Qg + (size_t)(q0 + r) * DM + c);
        Qs[c + 0][r] = f2tf32(v.x);
        Qs[c + 1][r] = f2tf32(v.y);
        Qs[c + 2][r] = f2tf32(v.z);
        Qs[c + 3][r] = f2tf32(v.w);
        float4 w = *(const float4*)(Kg + (size_t)(c0 + r) * DM + c);
        Ks[c + 0][r] = f2tf32(w.x);
        Ks[c + 1][r] = f2tf32(w.y);
        Ks[c + 2][r] = f2tf32(w.z);
        Ks[c + 3][r] = f2tf32(w.w);
    }
    __syncthreads();

    float acc[4][4][4] = {};
    #pragma unroll
    for (int ks = 0; ks < 64; ks += 8) {
        const int kb = ks + lq;
        uint32_t af[4][4], bf[4][2];
        #pragma unroll
        for (int mt = 0; mt < 4; mt++) {
            int m = wm0 + mt * 16 + g;
            af[mt][0] = Qs[kb][m];
            af[mt][1] = Qs[kb][m + 8];
            af[mt][2] = Qs[kb + 4][m];
            af[mt][3] = Qs[kb + 4][m + 8];
        }
        #pragma unroll
        for (int nt = 0; nt < 4; nt++) {
            int n = wn0 + nt * 8 + g;
            bf[nt][0] = Ks[kb][n];
            bf[nt][1] = Ks[kb + 4][n];
        }
        #pragma unroll
        for (int mt = 0; mt < 4; mt++)
            #pragma unroll
            for (int nt = 0; nt < 4; nt++)
                mma8(acc[mt][nt], af[mt], bf[nt]);
    }

    const int* mrow = mask + b * SEQ;
    float* C = P + (size_t)z * SEQ * SEQ;
    float rs[4][2] = {};
    #pragma unroll
    for (int nt = 0; nt < 4; nt++) {
        int ccol = c0 + wn0 + nt * 8 + 2 * lq;
        float m0 = (mrow[ccol] != 0) ? 1.f : 0.f;
        float m1 = (mrow[ccol + 1] != 0) ? 1.f : 0.f;
        #pragma unroll
        for (int mt = 0; mt < 4; mt++) {
            int r = q0 + wm0 + mt * 16 + g;
            float p0 = m0 * __expf(acc[mt][nt][0] * ATT_SCALE);
            float p1 = m1 * __expf(acc[mt][nt][1] * ATT_SCALE);
            float p2 = m0 * __expf(acc[mt][nt][2] * ATT_SCALE);
            float p3 = m1 * __expf(acc[mt][nt][3] * ATT_SCALE);
            float2 w0 = { p0, p1 }, w1 = { p2, p3 };
            *(float2*)&C[(size_t)r * SEQ + ccol]       = w0;
            *(float2*)&C[(size_t)(r + 8) * SEQ + ccol] = w1;
            rs[mt][0] += p0 + p1;
            rs[mt][1] += p2 + p3;
        }
    }

    #pragma unroll
    for (int mt = 0; mt < 4; mt++)
        #pragma unroll
        for (int hh = 0; hh < 2; hh++) {
            float v = rs[mt][hh];
            v += __shfl_xor_sync(0xffffffffu, v, 1);
            v += __shfl_xor_sync(0xffffffffu, v, 2);
            if (lq == 0)
                atomicAdd(&srow[wm0 + mt * 16 + hh * 8 + g], v);
        }
    __syncthreads();
    if (tid < 128)
        atomicAdd(&g_rowl[(size_t)z * SEQ + q0 + tid], srow[tid]);
}

// ===========================================================================
// pv_norm v3: cp.async 4-stage pipeline, 32-key chunks.
// Reads raw P, writes normalized probs in place, O = (P V) * inv_l -> atomics.
// grid = (16 q-blocks, 4 key-splits, 24) = 1536 CTAs, 256 thr, warps 4x2.
// Stage smem: Praw[128][36] fp32 (pad->conflict-free frags), V[32][72] fp32.
// ===========================================================================
#define PV_CH      32
#define PV_NCHUNK  (KEYS_PER_SPLIT / PV_CH)   // 16
#define PV_PROW    36
#define PV_VROW    72
#define PV_PSTG    (128 * PV_PROW)            // 4608 words
#define PV_VSTG    (PV_CH * PV_VROW)          // 2304 words
#define PV_STGW    (PV_PSTG + PV_VSTG)        // 6912 words
#define PV_SMEM_BYTES (4 * PV_STGW * 4 + 512) // 111104

__global__ __launch_bounds__(256, 2) void pv_norm(float* __restrict__ probs)
{
    extern __shared__ float sm[];
    float* inv_l = sm + 4 * PV_STGW;

    const int tid = threadIdx.x, lane = tid & 31, warp = tid >> 5;
    const int g = lane >> 2, lq = lane & 3;
    const int wm0 = (warp & 3) * 32, wn0 = (warp >> 2) * 32;
    const int z = blockIdx.z, b = z / NH, h = z % NH;
    const int q0 = blockIdx.x * 128;
    const int k_base = blockIdx.y * KEYS_PER_SPLIT;

    float* Pg = probs + (size_t)z * SEQ * SEQ + (size_t)q0 * SEQ;
    const float* Vg = g_v + (size_t)b * SEQ * DM + h * DHD;

    if (tid < 128)
        inv_l[tid] = 1.f / g_rowl[(size_t)z * SEQ + q0 + tid];

    // cp.async issue for chunk ch into stage ch&3
    auto issue = [&](int ch) {
        float* Pst = sm + (ch & 3) * PV_STGW;
        float* Vst = Pst + PV_PSTG;
        const int kb0 = k_base + ch * PV_CH;
        #pragma unroll
        for (int t = 0; t < 4; t++) {           // P: 128 rows x 32 = 1024 x16B
            int i = tid + t * 256;
            int r = i >> 3, cf = (i & 7) * 4;
            cp16(smem_u32(Pst + r * PV_PROW + cf),
                 Pg + (size_t)r * SEQ + kb0 + cf);
        }
        #pragma unroll
        for (int t = 0; t < 2; t++) {           // V: 32 rows x 64 = 512 x16B
            int i = tid + t * 256;
            int k = i >> 4, cf = (i & 15) * 4;
            cp16(smem_u32(Vst + k * PV_VROW + cf),
                 Vg + (size_t)(kb0 + k) * DM + cf);
        }
    };

    issue(0); cp_commit();
    issue(1); cp_commit();
    issue(2); cp_commit();

    float oacc[2][4][4] = {};

    for (int c = 0; c < PV_NCHUNK; c++) {
        cp_wait<2>();
        __syncthreads();
        // prefetch chunk c+3 into the buffer processed LAST iteration (safe)
        if (c + 3 < PV_NCHUNK) issue(c + 3);
        cp_commit();

        float* Pst = sm + (c & 3) * PV_STGW;
        float* Vst = Pst + PV_PSTG;

        // mma over this 32-key chunk (cvt fp32->tf32 inline)
        #pragma unroll
        for (int ksg = 0; ksg < 4; ksg++) {
            const int kb = ksg * 8 + lq;
            uint32_t af[2][4], bf[4][2];
            #pragma unroll
            for (int mt = 0; mt < 2; mt++) {
                int m = wm0 + mt * 16 + g;
                af[mt][0] = f2tf32(Pst[m * PV_PROW + kb]);
                af[mt][1] = f2tf32(Pst[(m + 8) * PV_PROW + kb]);
                af[mt][2] = f2tf32(Pst[m * PV_PROW + kb + 4]);
                af[mt][3] = f2tf32(Pst[(m + 8) * PV_PROW + kb + 4]);
            }
            #pragma unroll
            for (int nt = 0; nt < 4; nt++) {
                int n = wn0 + nt * 8 + g;
                bf[nt][0] = f2tf32(Vst[kb * PV_VROW + n]);
                bf[nt][1] = f2tf32(Vst[(kb + 4) * PV_VROW + n]);
            }
            #pragma unroll
            for (int mt = 0; mt < 2; mt++)
                #pragma unroll
                for (int nt = 0; nt < 4; nt++)
                    mma8(oacc[mt][nt], af[mt], bf[nt]);
        }

        // normalized probs write-back (fire-and-forget STG)
        const int kb0 = k_base + c * PV_CH;
        #pragma unroll
        for (int t = 0; t < 4; t++) {
            int i = tid + t * 256;
            int r = i >> 3, cf = (i & 7) * 4;
            float4 v = *(const float4*)(Pst + r * PV_PROW + cf);
            float iv = inv_l[r];
            float4 w = { v.x * iv, v.y * iv, v.z * iv, v.w * iv };
            *(float4*)(Pg + (size_t)r * SEQ + kb0 + cf) = w;
        }
    }

    // O = oacc * inv_l -> atomic accumulate
    float* Og = g_attn + (size_t)b * SEQ * DM + h * DHD + (size_t)q0 * DM;
    #pragma unroll
    for (int mt = 0; mt < 2; mt++) {
        int r = wm0 + mt * 16 + g;
        float i0 = inv_l[r], i1 = inv_l[r + 8];
        #pragma unroll
        for (int nt = 0; nt < 4; nt++) {
            int c = wn0 + nt * 8 + 2 * lq;
            atomicAdd(&Og[(size_t)r * DM + c],           oacc[mt][nt][0] * i0);
            atomicAdd(&Og[(size_t)r * DM + c + 1],       oacc[mt][nt][1] * i0);
            atomicAdd(&Og[(size_t)(r + 8) * DM + c],     oacc[mt][nt][2] * i1);
            atomicAdd(&Og[(size_t)(r + 8) * DM + c + 1], oacc[mt][nt][3] * i1);
        }
    }
}

// ---------------------------------------------------------------------------
extern "C" void kernel_launch(void* const* d_in, const int* in_sizes, int n_in,
                              void* d_out, int out_size)
{
    const float* query = (const float*)d_in[0];
    const float* key   = (const float*)d_in[1];
    const float* value = (const float*)d_in[2];
    const int*   mask  = (const int*)d_in[3];
    const float* wq = (const float*)d_in[4];
    const float* bq = (const float*)d_in[5];
    const float* wk = (const float*)d_in[6];
    const float* bk = (const float*)d_in[7];
    const float* wv = (const float*)d_in[8];
    const float* bv = (const float*)d_in[9];
    const float* wo = (const float*)d_in[10];
    const float* bo = (const float*)d_in[11];

    float* out   = (float*)d_out;                       // [B, S, D]
    float* probs = out + (size_t)BATCH * SEQ * DM;      // [B, H, S, S]

    cudaFuncSetAttribute(scores_exp,
                         cudaFuncAttributeMaxDynamicSharedMemorySize, SMS_BYTES);
    cudaFuncSetAttribute(pv_norm,
                         cudaFuncAttributeMaxDynamicSharedMemorySize, PV_SMEM_BYTES);

    init_zero<<<(BATCH * SEQ * DM + 255) / 256, 256>>>();

    dim3 qkv_grid(DM / 128, (BATCH * SEQ) / 64, 3);     // (6, 64, 3)
    qkv_proj<<<qkv_grid, 256>>>(query, key, value,
                                wq, bq, wk, bk, wv, bv);

    dim3 sc_grid(SEQ / 128, SEQ / 128, BATCH * NH);     // (16, 16, 24)
    scores_exp<<<sc_grid, 256, SMS_BYTES>>>(mask, probs);

    dim3 pv_grid(SEQ / 128, KSPLIT, BATCH * NH);        // (16, 4, 24)
    pv_norm<<<pv_grid, 256, PV_SMEM_BYTES>>>(probs);

    dim3 o_grid(DM / 128, (BATCH * SEQ) / 64);          // (6, 64)
    o_proj<<<o_grid, 256>>>(wo, bo, out);
}

// round 7
// speedup vs baseline: 1.8628x; 1.4679x over previous
#include <cuda_runtime.h>
#include <cstdint>
#include <cstddef>

// Problem constants
#define BATCH 2
#define SEQ   2048
#define DM    768
#define NH    12
#define DHD   64
#define ATT_SCALE 0.125f   // 1/sqrt(64)
#define KSPLIT 4
#define KEYS_PER_SPLIT (SEQ / KSPLIT)   // 512

// Scratch (allocation-free rule: __device__ globals)
__device__ float g_q[BATCH * SEQ * DM];
__device__ float g_k[BATCH * SEQ * DM];
__device__ float g_v[BATCH * SEQ * DM];
__device__ float g_attn[BATCH * SEQ * DM];
__device__ float g_rowl[BATCH * NH * SEQ];   // softmax row sums

// ---------------------------------------------------------------------------
// helpers
// ---------------------------------------------------------------------------
__device__ __forceinline__ uint32_t f2tf32(float f) {
    uint32_t u;
    asm("cvt.rna.tf32.f32 %0, %1;" : "=r"(u) : "f"(f));
    return u;
}

__device__ __forceinline__ void mma8(float* c, const uint32_t* a, const uint32_t* b) {
    asm volatile(
        "mma.sync.aligned.m16n8k8.row.col.f32.tf32.tf32.f32 "
        "{%0,%1,%2,%3},{%4,%5,%6,%7},{%8,%9},{%0,%1,%2,%3};"
        : "+f"(c[0]), "+f"(c[1]), "+f"(c[2]), "+f"(c[3])
        : "r"(a[0]), "r"(a[1]), "r"(a[2]), "r"(a[3]), "r"(b[0]), "r"(b[1]));
}

__device__ __forceinline__ uint32_t smem_u32(const void* p) {
    uint32_t a;
    asm("{ .reg .u64 t; cvta.to.shared.u64 t, %1; cvt.u32.u64 %0, t; }"
        : "=r"(a) : "l"(p));
    return a;
}

__device__ __forceinline__ void cp16(uint32_t dst, const void* src) {
    asm volatile("cp.async.cg.shared.global [%0], [%1], 16;" :: "r"(dst), "l"(src));
}
__device__ __forceinline__ void cp_commit() {
    asm volatile("cp.async.commit_group;");
}
template <int N>
__device__ __forceinline__ void cp_wait() {
    asm volatile("cp.async.wait_group %0;" :: "n"(N));
}

// ===========================================================================
// init: zero row sums and O accumulator
// ===========================================================================
__global__ void init_zero()
{
    int i = blockIdx.x * 256 + threadIdx.x;
    if (i < BATCH * NH * SEQ) g_rowl[i] = 0.f;
    if (i < BATCH * SEQ * DM) g_attn[i] = 0.f;
}

// ===========================================================================
// Projection core v2: 64x128 CTA tile, BK=32, 3-stage cp.async pipeline.
// 256 threads (8 warps 2x4; warp tile 32x32). Raw fp32 in smem, cvt at frag.
// Stage: A 64x32 (pad 36) + B(W) 128x32 (pad 36) = 27648 B; 3 stages.
// ===========================================================================
#define PJ_BK   32
#define PJ_ROWP 36
#define PJ_ASTG (64 * PJ_ROWP)            // 2304 words
#define PJ_BSTG (128 * PJ_ROWP)           // 4608 words
#define PJ_STGW (PJ_ASTG + PJ_BSTG)       // 6912 words
#define PJ_NK   (DM / PJ_BK)              // 24
#define PJ_SMEM_BYTES (3 * PJ_STGW * 4)   // 82944

__device__ __forceinline__ void proj_body(
    const float* __restrict__ X, const float* __restrict__ W,
    const float* __restrict__ bias, float* __restrict__ Y,
    int row0, int col0, float* sm)
{
    const int tid = threadIdx.x, lane = tid & 31, warp = tid >> 5;
    const int g = lane >> 2, lq = lane & 3;
    const int wm0 = (warp & 1) * 32, wn0 = (warp >> 1) * 32;
    const float* Ag = X + (size_t)row0 * DM;
    const float* Bg = W + (size_t)col0 * DM;

    auto issue = [&](int s) {
        float* Ast = sm + (s % 3) * PJ_STGW;
        float* Bst = Ast + PJ_ASTG;
        const int k0 = s * PJ_BK;
        #pragma unroll
        for (int t = 0; t < 2; t++) {          // A: 64 x 32 = 512 float4
            int i = tid + t * 256;
            int r = i >> 3, cf = (i & 7) * 4;
            cp16(smem_u32(Ast + r * PJ_ROWP + cf), Ag + (size_t)r * DM + k0 + cf);
        }
        #pragma unroll
        for (int t = 0; t < 4; t++) {          // B: 128 x 32 = 1024 float4
            int i = tid + t * 256;
            int r = i >> 3, cf = (i & 7) * 4;
            cp16(smem_u32(Bst + r * PJ_ROWP + cf), Bg + (size_t)r * DM + k0 + cf);
        }
    };

    float acc[2][4][4] = {};

    auto compute = [&](int s) {
        const float* Ast = sm + (s % 3) * PJ_STGW;
        const float* Bst = Ast + PJ_ASTG;
        #pragma unroll
        for (int ksg = 0; ksg < PJ_BK / 8; ksg++) {
            const int kb = ksg * 8 + lq;
            uint32_t af[2][4], bf[4][2];
            #pragma unroll
            for (int mt = 0; mt < 2; mt++) {
                int m = wm0 + mt * 16 + g;
                af[mt][0] = f2tf32(Ast[m * PJ_ROWP + kb]);
                af[mt][1] = f2tf32(Ast[(m + 8) * PJ_ROWP + kb]);
                af[mt][2] = f2tf32(Ast[m * PJ_ROWP + kb + 4]);
                af[mt][3] = f2tf32(Ast[(m + 8) * PJ_ROWP + kb + 4]);
            }
            #pragma unroll
            for (int nt = 0; nt < 4; nt++) {
                int n = wn0 + nt * 8 + g;
                bf[nt][0] = f2tf32(Bst[n * PJ_ROWP + kb]);
                bf[nt][1] = f2tf32(Bst[n * PJ_ROWP + kb + 4]);
            }
            #pragma unroll
            for (int mt = 0; mt < 2; mt++)
                #pragma unroll
                for (int nt = 0; nt < 4; nt++)
                    mma8(acc[mt][nt], af[mt], bf[nt]);
        }
    };

    issue(0); cp_commit();
    issue(1); cp_commit();

    for (int s = 0; s < PJ_NK; s++) {
        cp_wait<1>();
        __syncthreads();
        if (s + 2 < PJ_NK) issue(s + 2);
        cp_commit();
        compute(s);
    }

    #pragma unroll
    for (int mt = 0; mt < 2; mt++) {
        int r = row0 + wm0 + mt * 16 + g;
        #pragma unroll
        for (int nt = 0; nt < 4; nt++) {
            int ccol = col0 + wn0 + nt * 8 + 2 * lq;
            float2 bv = *(const float2*)&bias[ccol];
            float2 o0 = { acc[mt][nt][0] + bv.x, acc[mt][nt][1] + bv.y };
            float2 o1 = { acc[mt][nt][2] + bv.x, acc[mt][nt][3] + bv.y };
            *(float2*)&Y[(size_t)r * DM + ccol]       = o0;
            *(float2*)&Y[(size_t)(r + 8) * DM + ccol] = o1;
        }
    }
}

__global__ __launch_bounds__(256, 2) void qkv_proj(
    const float* __restrict__ q,  const float* __restrict__ k,
    const float* __restrict__ v,
    const float* __restrict__ wq, const float* __restrict__ bq,
    const float* __restrict__ wk, const float* __restrict__ bk,
    const float* __restrict__ wv, const float* __restrict__ bv)
{
    extern __shared__ float psm[];
    const int z = blockIdx.z;
    const float* X = (z == 0) ? q  : (z == 1) ? k  : v;
    const float* W = (z == 0) ? wq : (z == 1) ? wk : wv;
    const float* B = (z == 0) ? bq : (z == 1) ? bk : bv;
    float*       Y = (z == 0) ? g_q : (z == 1) ? g_k : g_v;
    proj_body(X, W, B, Y, blockIdx.y * 64, blockIdx.x * 128, psm);
}

__global__ __launch_bounds__(256, 2) void o_proj(
    const float* __restrict__ W, const float* __restrict__ bias,
    float* __restrict__ Y)
{
    extern __shared__ float psm[];
    proj_body(g_attn, W, bias, Y, blockIdx.y * 64, blockIdx.x * 128, psm);
}

// ===========================================================================
// scores_exp v2: P[z,q,k] = mask[k] * exp((Q.K^T)*scale)  (UNNORMALIZED),
// rowsums into g_rowl. cp.async loads, raw fp32 smem, cvt at fragment load.
// grid = (16, 16, 24), 256 threads, warp layout 2x4.
// Smem: Qst[128][68] | Kst[128][68] fp32 = 69632 B (+srow static).
// ===========================================================================
#define SC_ROWP 68
#define SC_TILE (128 * SC_ROWP)            // 8704 words
#define SMS_BYTES (2 * SC_TILE * 4)        // 69632

__global__ __launch_bounds__(256, 2) void scores_exp(
    const int* __restrict__ mask, float* __restrict__ P)
{
    extern __shared__ float ssm[];
    float* Qst = ssm;
    float* Kst = ssm + SC_TILE;
    __shared__ float srow[128];

    const int tid = threadIdx.x, lane = tid & 31, warp = tid >> 5;
    const int g = lane >> 2, lq = lane & 3;
    const int wm0 = (warp & 1) * 64, wn0 = (warp >> 1) * 32;
    const int z = blockIdx.z, b = z / NH, h = z % NH;
    const int q0 = blockIdx.y * 128, c0 = blockIdx.x * 128;

    const float* Qg = g_q + (size_t)b * SEQ * DM + h * DHD;
    const float* Kg = g_k + (size_t)b * SEQ * DM + h * DHD;

    if (tid < 128) srow[tid] = 0.f;

    // cp.async both tiles: 128 rows x 64 cols = 2048 float4 each
    #pragma unroll
    for (int t = 0; t < 8; t++) {
        int i = tid + t * 256;
        int r = i >> 4, cf = (i & 15) * 4;
        cp16(smem_u32(Qst + r * SC_ROWP + cf), Qg + (size_t)(q0 + r) * DM + cf);
        cp16(smem_u32(Kst + r * SC_ROWP + cf), Kg + (size_t)(c0 + r) * DM + cf);
    }
    cp_commit();
    cp_wait<0>();
    __syncthreads();

    float acc[4][4][4] = {};
    #pragma unroll
    for (int ksg = 0; ksg < 8; ksg++) {
        const int kb = ksg * 8 + lq;
        uint32_t af[4][4], bf[4][2];
        #pragma unroll
        for (int mt = 0; mt < 4; mt++) {
            int m = wm0 + mt * 16 + g;
            af[mt][0] = f2tf32(Qst[m * SC_ROWP + kb]);
            af[mt][1] = f2tf32(Qst[(m + 8) * SC_ROWP + kb]);
            af[mt][2] = f2tf32(Qst[m * SC_ROWP + kb + 4]);
            af[mt][3] = f2tf32(Qst[(m + 8) * SC_ROWP + kb + 4]);
        }
        #pragma unroll
        for (int nt = 0; nt < 4; nt++) {
            int n = wn0 + nt * 8 + g;
            bf[nt][0] = f2tf32(Kst[n * SC_ROWP + kb]);
            bf[nt][1] = f2tf32(Kst[n * SC_ROWP + kb + 4]);
        }
        #pragma unroll
        for (int mt = 0; mt < 4; mt++)
            #pragma unroll
            for (int nt = 0; nt < 4; nt++)
                mma8(acc[mt][nt], af[mt], bf[nt]);
    }

    const int* mrow = mask + b * SEQ;
    float* C = P + (size_t)z * SEQ * SEQ;
    float rs[4][2] = {};
    #pragma unroll
    for (int nt = 0; nt < 4; nt++) {
        int ccol = c0 + wn0 + nt * 8 + 2 * lq;
        float m0 = (mrow[ccol] != 0) ? 1.f : 0.f;
        float m1 = (mrow[ccol + 1] != 0) ? 1.f : 0.f;
        #pragma unroll
        for (int mt = 0; mt < 4; mt++) {
            int r = q0 + wm0 + mt * 16 + g;
            float p0 = m0 * __expf(acc[mt][nt][0] * ATT_SCALE);
            float p1 = m1 * __expf(acc[mt][nt][1] * ATT_SCALE);
            float p2 = m0 * __expf(acc[mt][nt][2] * ATT_SCALE);
            float p3 = m1 * __expf(acc[mt][nt][3] * ATT_SCALE);
            float2 w0 = { p0, p1 }, w1 = { p2, p3 };
            *(float2*)&C[(size_t)r * SEQ + ccol]       = w0;
            *(float2*)&C[(size_t)(r + 8) * SEQ + ccol] = w1;
            rs[mt][0] += p0 + p1;
            rs[mt][1] += p2 + p3;
        }
    }

    #pragma unroll
    for (int mt = 0; mt < 4; mt++)
        #pragma unroll
        for (int hh = 0; hh < 2; hh++) {
            float v = rs[mt][hh];
            v += __shfl_xor_sync(0xffffffffu, v, 1);
            v += __shfl_xor_sync(0xffffffffu, v, 2);
            if (lq == 0)
                atomicAdd(&srow[wm0 + mt * 16 + hh * 8 + g], v);
        }
    __syncthreads();
    if (tid < 128)
        atomicAdd(&g_rowl[(size_t)z * SEQ + q0 + tid], srow[tid]);
}

// ===========================================================================
// pv_norm v3 (unchanged from R6): cp.async 4-stage pipeline, 32-key chunks.
// ===========================================================================
#define PV_CH      32
#define PV_NCHUNK  (KEYS_PER_SPLIT / PV_CH)   // 16
#define PV_PROW    36
#define PV_VROW    72
#define PV_PSTG    (128 * PV_PROW)            // 4608 words
#define PV_VSTG    (PV_CH * PV_VROW)          // 2304 words
#define PV_STGW    (PV_PSTG + PV_VSTG)        // 6912 words
#define PV_SMEM_BYTES (4 * PV_STGW * 4 + 512) // 111104

__global__ __launch_bounds__(256, 2) void pv_norm(float* __restrict__ probs)
{
    extern __shared__ float sm[];
    float* inv_l = sm + 4 * PV_STGW;

    const int tid = threadIdx.x, lane = tid & 31, warp = tid >> 5;
    const int g = lane >> 2, lq = lane & 3;
    const int wm0 = (warp & 3) * 32, wn0 = (warp >> 2) * 32;
    const int z = blockIdx.z, b = z / NH, h = z % NH;
    const int q0 = blockIdx.x * 128;
    const int k_base = blockIdx.y * KEYS_PER_SPLIT;

    float* Pg = probs + (size_t)z * SEQ * SEQ + (size_t)q0 * SEQ;
    const float* Vg = g_v + (size_t)b * SEQ * DM + h * DHD;

    if (tid < 128)
        inv_l[tid] = 1.f / g_rowl[(size_t)z * SEQ + q0 + tid];

    auto issue = [&](int ch) {
        float* Pst = sm + (ch & 3) * PV_STGW;
        float* Vst = Pst + PV_PSTG;
        const int kb0 = k_base + ch * PV_CH;
        #pragma unroll
        for (int t = 0; t < 4; t++) {
            int i = tid + t * 256;
            int r = i >> 3, cf = (i & 7) * 4;
            cp16(smem_u32(Pst + r * PV_PROW + cf),
                 Pg + (size_t)r * SEQ + kb0 + cf);
        }
        #pragma unroll
        for (int t = 0; t < 2; t++) {
            int i = tid + t * 256;
            int k = i >> 4, cf = (i & 15) * 4;
            cp16(smem_u32(Vst + k * PV_VROW + cf),
                 Vg + (size_t)(kb0 + k) * DM + cf);
        }
    };

    issue(0); cp_commit();
    issue(1); cp_commit();
    issue(2); cp_commit();

    float oacc[2][4][4] = {};

    for (int c = 0; c < PV_NCHUNK; c++) {
        cp_wait<2>();
        __syncthreads();
        if (c + 3 < PV_NCHUNK) issue(c + 3);
        cp_commit();

        float* Pst = sm + (c & 3) * PV_STGW;
        float* Vst = Pst + PV_PSTG;

        #pragma unroll
        for (int ksg = 0; ksg < 4; ksg++) {
            const int kb = ksg * 8 + lq;
            uint32_t af[2][4], bf[4][2];
            #pragma unroll
            for (int mt = 0; mt < 2; mt++) {
                int m = wm0 + mt * 16 + g;
                af[mt][0] = f2tf32(Pst[m * PV_PROW + kb]);
                af[mt][1] = f2tf32(Pst[(m + 8) * PV_PROW + kb]);
                af[mt][2] = f2tf32(Pst[m * PV_PROW + kb + 4]);
                af[mt][3] = f2tf32(Pst[(m + 8) * PV_PROW + kb + 4]);
            }
            #pragma unroll
            for (int nt = 0; nt < 4; nt++) {
                int n = wn0 + nt * 8 + g;
                bf[nt][0] = f2tf32(Vst[kb * PV_VROW + n]);
                bf[nt][1] = f2tf32(Vst[(kb + 4) * PV_VROW + n]);
            }
            #pragma unroll
            for (int mt = 0; mt < 2; mt++)
                #pragma unroll
                for (int nt = 0; nt < 4; nt++)
                    mma8(oacc[mt][nt], af[mt], bf[nt]);
        }

        const int kb0 = k_base + c * PV_CH;
        #pragma unroll
        for (int t = 0; t < 4; t++) {
            int i = tid + t * 256;
            int r = i >> 3, cf = (i & 7) * 4;
            float4 v = *(const float4*)(Pst + r * PV_PROW + cf);
            float iv = inv_l[r];
            float4 w = { v.x * iv, v.y * iv, v.z * iv, v.w * iv };
            *(float4*)(Pg + (size_t)r * SEQ + kb0 + cf) = w;
        }
    }

    float* Og = g_attn + (size_t)b * SEQ * DM + h * DHD + (size_t)q0 * DM;
    #pragma unroll
    for (int mt = 0; mt < 2; mt++) {
        int r = wm0 + mt * 16 + g;
        float i0 = inv_l[r], i1 = inv_l[r + 8];
        #pragma unroll
        for (int nt = 0; nt < 4; nt++) {
            int c = wn0 + nt * 8 + 2 * lq;
            atomicAdd(&Og[(size_t)r * DM + c],           oacc[mt][nt][0] * i0);
            atomicAdd(&Og[(size_t)r * DM + c + 1],       oacc[mt][nt][1] * i0);
            atomicAdd(&Og[(size_t)(r + 8) * DM + c],     oacc[mt][nt][2] * i1);
            atomicAdd(&Og[(size_t)(r + 8) * DM + c + 1], oacc[mt][nt][3] * i1);
        }
    }
}

// ---------------------------------------------------------------------------
extern "C" void kernel_launch(void* const* d_in, const int* in_sizes, int n_in,
                              void* d_out, int out_size)
{
    const float* query = (const float*)d_in[0];
    const float* key   = (const float*)d_in[1];
    const float* value = (const float*)d_in[2];
    const int*   mask  = (const int*)d_in[3];
    const float* wq = (const float*)d_in[4];
    const float* bq = (const float*)d_in[5];
    const float* wk = (const float*)d_in[6];
    const float* bk = (const float*)d_in[7];
    const float* wv = (const float*)d_in[8];
    const float* bv = (const float*)d_in[9];
    const float* wo = (const float*)d_in[10];
    const float* bo = (const float*)d_in[11];

    float* out   = (float*)d_out;                       // [B, S, D]
    float* probs = out + (size_t)BATCH * SEQ * DM;      // [B, H, S, S]

    cudaFuncSetAttribute(qkv_proj,
                         cudaFuncAttributeMaxDynamicSharedMemorySize, PJ_SMEM_BYTES);
    cudaFuncSetAttribute(o_proj,
                         cudaFuncAttributeMaxDynamicSharedMemorySize, PJ_SMEM_BYTES);
    cudaFuncSetAttribute(scores_exp,
                         cudaFuncAttributeMaxDynamicSharedMemorySize, SMS_BYTES);
    cudaFuncSetAttribute(pv_norm,
                         cudaFuncAttributeMaxDynamicSharedMemorySize, PV_SMEM_BYTES);

    init_zero<<<(BATCH * SEQ * DM + 255) / 256, 256>>>();

    dim3 qkv_grid(DM / 128, (BATCH * SEQ) / 64, 3);     // (6, 64, 3)
    qkv_proj<<<qkv_grid, 256, PJ_SMEM_BYTES>>>(query, key, value,
                                               wq, bq, wk, bk, wv, bv);

    dim3 sc_grid(SEQ / 128, SEQ / 128, BATCH * NH);     // (16, 16, 24)
    scores_exp<<<sc_grid, 256, SMS_BYTES>>>(mask, probs);

    dim3 pv_grid(SEQ / 128, KSPLIT, BATCH * NH);        // (16, 4, 24)
    pv_norm<<<pv_grid, 256, PV_SMEM_BYTES>>>(probs);

    dim3 o_grid(DM / 128, (BATCH * SEQ) / 64);          // (6, 64)
    o_proj<<<o_grid, 256, PJ_SMEM_BYTES>>>(wo, bo, out);
}